// round 8
// baseline (speedup 1.0000x reference)
#include <cuda_runtime.h>
#include <cuda_bf16.h>
#include <math.h>
#include <stdint.h>

// ---------------------------------------------------------------------------
// Problem constants
// ---------------------------------------------------------------------------
#define BATCH 8
#define SEQ   1024
#define TOK   (BATCH * SEQ)        // 8192 tokens
#define DIM   768
#define HEADS 12
#define HD    64
#define KP    64
#define MLPH  3072
#define QKVD  (3 * DIM)            // 2304
#define LN_EPS 1e-5f

// ---------------------------------------------------------------------------
// Scratch (device globals; no allocations allowed)
// ---------------------------------------------------------------------------
__device__ __align__(256) float g_n1  [TOK * DIM];
__device__ __align__(256) float g_rinv[TOK];
__device__ __align__(256) float g_pn  [KP * DIM];
__device__ __align__(256) float g_y   [TOK * DIM];
__device__ __align__(256) float g_z   [TOK * DIM];
__device__ __align__(256) float g_dmap[TOK * KP];
__device__ __align__(256) float g_cph [TOK * KP];
__device__ __align__(256) float g_xsum[TOK * DIM];

__device__ __align__(256) __nv_bfloat16 g_qkvh[TOK * QKVD];
__device__ __align__(256) __nv_bfloat16 g_qkvl[TOK * QKVD];

__device__ __align__(256) __nv_bfloat16 g_n1h [TOK * DIM];
__device__ __align__(256) __nv_bfloat16 g_n1l [TOK * DIM];
__device__ __align__(256) __nv_bfloat16 g_aoh [TOK * DIM];
__device__ __align__(256) __nv_bfloat16 g_aol [TOK * DIM];
__device__ __align__(256) __nv_bfloat16 g_zinh[TOK * DIM];
__device__ __align__(256) __nv_bfloat16 g_zinl[TOK * DIM];
__device__ __align__(256) __nv_bfloat16 g_n2h [TOK * DIM];
__device__ __align__(256) __nv_bfloat16 g_n2l [TOK * DIM];
__device__ __align__(256) __nv_bfloat16 g_hh  [TOK * MLPH];
__device__ __align__(256) __nv_bfloat16 g_hl  [TOK * MLPH];

__device__ __align__(256) __nv_bfloat16 g_wqkvh [QKVD * DIM];
__device__ __align__(256) __nv_bfloat16 g_wqkvl [QKVD * DIM];
__device__ __align__(256) __nv_bfloat16 g_wprojh[DIM * DIM];
__device__ __align__(256) __nv_bfloat16 g_wprojl[DIM * DIM];
__device__ __align__(256) __nv_bfloat16 g_wcqkvh[QKVD * DIM];
__device__ __align__(256) __nv_bfloat16 g_wcqkvl[QKVD * DIM];
__device__ __align__(256) __nv_bfloat16 g_wcprojh[DIM * DIM];
__device__ __align__(256) __nv_bfloat16 g_wcprojl[DIM * DIM];
__device__ __align__(256) __nv_bfloat16 g_wfc1h[MLPH * DIM];
__device__ __align__(256) __nv_bfloat16 g_wfc1l[MLPH * DIM];
__device__ __align__(256) __nv_bfloat16 g_wfc2h[DIM * MLPH];
__device__ __align__(256) __nv_bfloat16 g_wfc2l[DIM * MLPH];

// ---------------------------------------------------------------------------
// Helpers
// ---------------------------------------------------------------------------
__device__ __forceinline__ float gelu_exact(float v) {
    return 0.5f * v * (1.0f + erff(v * 0.70710678118654752f));
}

__device__ __forceinline__ void split_bf16(float v, __nv_bfloat16& hi, __nv_bfloat16& lo) {
    hi = __float2bfloat16(v);
    lo = __float2bfloat16(v - __bfloat162float(hi));
}

__device__ __forceinline__ uint32_t pack2(__nv_bfloat16 lo, __nv_bfloat16 hi) {
    __nv_bfloat162 t;
    t.x = lo; t.y = hi;
    return *(uint32_t*)&t;
}

__device__ __forceinline__ float block_sum256(float v, float* red) {
    int tid = threadIdx.x;
    red[tid] = v;
    __syncthreads();
    #pragma unroll
    for (int s = 128; s > 0; s >>= 1) {
        if (tid < s) red[tid] += red[tid + s];
        __syncthreads();
    }
    float r = red[0];
    __syncthreads();
    return r;
}

__device__ __forceinline__ uint32_t smem_u32(const void* p) {
    uint32_t a;
    asm("{ .reg .u64 t; cvta.to.shared.u64 t, %1; cvt.u32.u64 %0, t; }" : "=r"(a) : "l"(p));
    return a;
}

__device__ __forceinline__ void cp_async16(uint32_t dst, const void* src) {
    asm volatile("cp.async.cg.shared.global [%0], [%1], 16;" :: "r"(dst), "l"(src));
}

__device__ __forceinline__ void ldmatrix_x4(uint32_t& r0, uint32_t& r1,
                                            uint32_t& r2, uint32_t& r3, uint32_t addr) {
    asm volatile("ldmatrix.sync.aligned.m8n8.x4.shared.b16 {%0,%1,%2,%3}, [%4];"
                 : "=r"(r0), "=r"(r1), "=r"(r2), "=r"(r3) : "r"(addr));
}

__device__ __forceinline__ void ldmatrix_x4t(uint32_t& r0, uint32_t& r1,
                                             uint32_t& r2, uint32_t& r3, uint32_t addr) {
    asm volatile("ldmatrix.sync.aligned.m8n8.x4.trans.shared.b16 {%0,%1,%2,%3}, [%4];"
                 : "=r"(r0), "=r"(r1), "=r"(r2), "=r"(r3) : "r"(addr));
}

__device__ __forceinline__ void mma_bf16(float* d, const uint32_t* a, uint32_t b0, uint32_t b1) {
    asm volatile(
        "mma.sync.aligned.m16n8k16.row.col.f32.bf16.bf16.f32 "
        "{%0,%1,%2,%3}, {%4,%5,%6,%7}, {%8,%9}, {%0,%1,%2,%3};"
        : "+f"(d[0]), "+f"(d[1]), "+f"(d[2]), "+f"(d[3])
        : "r"(a[0]), "r"(a[1]), "r"(a[2]), "r"(a[3]), "r"(b0), "r"(b1));
}

// swizzled offset inside a 128-byte-row tile, 16-byte granularity
__device__ __forceinline__ uint32_t sw_off(int r, int c16) {
    return (uint32_t)(r * 128 + ((c16 * 16) ^ ((r & 7) << 4)));
}

// ---------------------------------------------------------------------------
// Elementwise kernels
// ---------------------------------------------------------------------------
__global__ void cvt_kernel(const float* __restrict__ w,
                           __nv_bfloat16* __restrict__ hi,
                           __nv_bfloat16* __restrict__ lo, int n4) {
    int i = blockIdx.x * blockDim.x + threadIdx.x;
    if (i < n4) {
        float4 v = *(const float4*)(w + i * 4);
        __nv_bfloat16 h0, l0, h1, l1, h2, l2, h3, l3;
        split_bf16(v.x, h0, l0); split_bf16(v.y, h1, l1);
        split_bf16(v.z, h2, l2); split_bf16(v.w, h3, l3);
        *(uint2*)(hi + i * 4) = make_uint2(pack2(h0, h1), pack2(h2, h3));
        *(uint2*)(lo + i * 4) = make_uint2(pack2(l0, l1), pack2(l2, l3));
    }
}

__global__ void ln_kernel(const float* __restrict__ x,
                          const float* __restrict__ g,
                          const float* __restrict__ b,
                          float* __restrict__ out,
                          __nv_bfloat16* __restrict__ ohi,
                          __nv_bfloat16* __restrict__ olo,
                          float* __restrict__ rinv) {
    __shared__ float red[256];
    int row = blockIdx.x;
    int tid = threadIdx.x;
    size_t base = (size_t)row * DIM;

    float v0 = x[base + tid];
    float v1 = x[base + 256 + tid];
    float v2 = x[base + 512 + tid];

    float mu = block_sum256(v0 + v1 + v2, red) * (1.0f / DIM);
    float d0 = v0 - mu, d1 = v1 - mu, d2 = v2 - mu;
    float var = block_sum256(d0 * d0 + d1 * d1 + d2 * d2, red) * (1.0f / DIM);
    float inv = rsqrtf(var + LN_EPS);

    float t0 = d0 * inv * g[tid]       + b[tid];
    float t1 = d1 * inv * g[tid + 256] + b[tid + 256];
    float t2 = d2 * inv * g[tid + 512] + b[tid + 512];
    out[base + tid] = t0; out[base + 256 + tid] = t1; out[base + 512 + tid] = t2;

    __nv_bfloat16 h, l;
    split_bf16(t0, h, l); ohi[base + tid] = h;       olo[base + tid] = l;
    split_bf16(t1, h, l); ohi[base + 256 + tid] = h; olo[base + 256 + tid] = l;
    split_bf16(t2, h, l); ohi[base + 512 + tid] = h; olo[base + 512 + tid] = l;

    float s2 = block_sum256(t0 * t0 + t1 * t1 + t2 * t2, red);
    if (tid == 0) rinv[row] = rsqrtf(s2);
}

__global__ void addln_kernel(const float* __restrict__ x,
                             const float* __restrict__ y,
                             const float* __restrict__ z,
                             const float* __restrict__ g,
                             const float* __restrict__ b,
                             float* __restrict__ xsum,
                             __nv_bfloat16* __restrict__ n2h,
                             __nv_bfloat16* __restrict__ n2l) {
    __shared__ float red[256];
    int row = blockIdx.x;
    int tid = threadIdx.x;
    size_t base = (size_t)row * DIM;

    float v0 = x[base + tid]       + y[base + tid]       + z[base + tid];
    float v1 = x[base + 256 + tid] + y[base + 256 + tid] + z[base + 256 + tid];
    float v2 = x[base + 512 + tid] + y[base + 512 + tid] + z[base + 512 + tid];
    xsum[base + tid] = v0; xsum[base + 256 + tid] = v1; xsum[base + 512 + tid] = v2;

    float mu = block_sum256(v0 + v1 + v2, red) * (1.0f / DIM);
    float d0 = v0 - mu, d1 = v1 - mu, d2 = v2 - mu;
    float var = block_sum256(d0 * d0 + d1 * d1 + d2 * d2, red) * (1.0f / DIM);
    float inv = rsqrtf(var + LN_EPS);

    float t0 = d0 * inv * g[tid]       + b[tid];
    float t1 = d1 * inv * g[tid + 256] + b[tid + 256];
    float t2 = d2 * inv * g[tid + 512] + b[tid + 512];

    __nv_bfloat16 h, l;
    split_bf16(t0, h, l); n2h[base + tid] = h;       n2l[base + tid] = l;
    split_bf16(t1, h, l); n2h[base + 256 + tid] = h; n2l[base + 256 + tid] = l;
    split_bf16(t2, h, l); n2h[base + 512 + tid] = h; n2l[base + 512 + tid] = l;
}

__global__ void pn_kernel(const float* __restrict__ P, float* __restrict__ pn) {
    __shared__ float red[256];
    int row = blockIdx.x;
    int tid = threadIdx.x;
    size_t base = (size_t)row * DIM;
    float v0 = P[base + tid], v1 = P[base + 256 + tid], v2 = P[base + 512 + tid];
    float s2 = block_sum256(v0 * v0 + v1 * v1 + v2 * v2, red);
    float inv = rsqrtf(s2);
    pn[base + tid] = v0 * inv;
    pn[base + 256 + tid] = v1 * inv;
    pn[base + 512 + tid] = v2 * inv;
}

// ---------------------------------------------------------------------------
// fp32 SGEMM for small GEMMs: C[M,N] = A[M,K] @ B[N,K]^T
// ---------------------------------------------------------------------------
template <int ACT, bool BIAS, bool RSCALE, bool BF16OUT>
__global__ void sgemm64(const float* __restrict__ A,
                        const float* __restrict__ B,
                        const float* __restrict__ bias,
                        const float* __restrict__ rs,
                        float* __restrict__ C,
                        __nv_bfloat16* __restrict__ Chi,
                        __nv_bfloat16* __restrict__ Clo,
                        int M, int N, int K) {
    __shared__ float As[16][65];
    __shared__ float Bs[16][65];

    int tid = threadIdx.x;
    int m0 = blockIdx.y * 64;
    int n0 = blockIdx.x * 64;
    int ty = tid >> 4, tx = tid & 15;
    int lrow = tid >> 2;
    int lk   = (tid & 3) * 4;

    const float* Ap = A + (size_t)(m0 + lrow) * K + lk;
    const float* Bp = B + (size_t)(n0 + lrow) * K + lk;

    float acc[4][4];
    #pragma unroll
    for (int i = 0; i < 4; i++)
        #pragma unroll
        for (int j = 0; j < 4; j++) acc[i][j] = 0.0f;

    for (int k0 = 0; k0 < K; k0 += 16) {
        float4 av = *(const float4*)(Ap + k0);
        float4 bv = *(const float4*)(Bp + k0);
        As[lk + 0][lrow] = av.x; As[lk + 1][lrow] = av.y;
        As[lk + 2][lrow] = av.z; As[lk + 3][lrow] = av.w;
        Bs[lk + 0][lrow] = bv.x; Bs[lk + 1][lrow] = bv.y;
        Bs[lk + 2][lrow] = bv.z; Bs[lk + 3][lrow] = bv.w;
        __syncthreads();

        #pragma unroll
        for (int kk = 0; kk < 16; kk++) {
            float a[4], bb[4];
            #pragma unroll
            for (int i = 0; i < 4; i++) a[i]  = As[kk][ty * 4 + i];
            #pragma unroll
            for (int j = 0; j < 4; j++) bb[j] = Bs[kk][tx * 4 + j];
            #pragma unroll
            for (int i = 0; i < 4; i++)
                #pragma unroll
                for (int j = 0; j < 4; j++)
                    acc[i][j] = fmaf(a[i], bb[j], acc[i][j]);
        }
        __syncthreads();
    }

    #pragma unroll
    for (int i = 0; i < 4; i++) {
        int row = m0 + ty * 4 + i;
        float rsv = RSCALE ? rs[row] : 1.0f;
        #pragma unroll
        for (int j = 0; j < 4; j++) {
            int col = n0 + tx * 4 + j;
            float v = acc[i][j];
            if (BIAS) v += bias[col];
            if (ACT == 1) v = gelu_exact(v);
            if (RSCALE) v *= rsv;
            if (BF16OUT) {
                __nv_bfloat16 h, l;
                split_bf16(v, h, l);
                Chi[(size_t)row * N + col] = h;
                Clo[(size_t)row * N + col] = l;
            } else {
                C[(size_t)row * N + col] = v;
            }
        }
    }
}

// ---------------------------------------------------------------------------
// HMMA split-bf16 GEMM v2: 256x128 tile, 512 threads (16 warps, 8m x 2n),
// K-chunk 64 bf16 (SW128), cp.async double buffer (192KB smem).
// Stage layout: Ah(32K) | Al(32K) | Bh(16K) | Bl(16K); stage stride 96K.
// ---------------------------------------------------------------------------
#define HG_SMEM (2 * 98304)   // 196608

template <int ACT, bool ADD, bool OUTF32, bool OUTBF16>
__global__ void __launch_bounds__(512, 1)
hgemm(const __nv_bfloat16* __restrict__ Ah, const __nv_bfloat16* __restrict__ Al,
      const __nv_bfloat16* __restrict__ Bh, const __nv_bfloat16* __restrict__ Bl,
      const float* __restrict__ bias, const float* __restrict__ addp,
      float* __restrict__ C,
      __nv_bfloat16* __restrict__ Chi, __nv_bfloat16* __restrict__ Clo,
      int M, int N, int K) {
    extern __shared__ char smem[];
    uint32_t sb = smem_u32(smem);

    int tid = threadIdx.x;
    int wid = tid >> 5, lane = tid & 31;
    int wm = wid >> 1, wn = wid & 1;          // wm 0..7, wn 0..1
    int g = lane >> 3, lr = lane & 7;

    int m0 = blockIdx.y * 256, n0 = blockIdx.x * 128;
    int nc = K >> 6;

    uint32_t aPre[2], aXr[2];
    #pragma unroll
    for (int mf = 0; mf < 2; mf++) {
        int r = wm * 32 + mf * 16 + (g & 1) * 8 + lr;
        aPre[mf] = (uint32_t)(r * 128);
        aXr[mf]  = (uint32_t)((r & 7) << 4);
    }
    int acb = g >> 1;
    uint32_t bPre[4], bXr[4];
    #pragma unroll
    for (int p = 0; p < 4; p++) {
        int r = wn * 64 + p * 16 + (g >> 1) * 8 + lr;
        bPre[p] = (uint32_t)(r * 128);
        bXr[p]  = (uint32_t)((r & 7) << 4);
    }
    int bcb = g & 1;

    const __nv_bfloat16* Ah_g = Ah + (size_t)m0 * K;
    const __nv_bfloat16* Al_g = Al + (size_t)m0 * K;
    const __nv_bfloat16* Bh_g = Bh + (size_t)n0 * K;
    const __nv_bfloat16* Bl_g = Bl + (size_t)n0 * K;

    float acc[2][8][4];
    #pragma unroll
    for (int mf = 0; mf < 2; mf++)
        #pragma unroll
        for (int nf = 0; nf < 8; nf++)
            #pragma unroll
            for (int q = 0; q < 4; q++) acc[mf][nf][q] = 0.0f;

    // chunk load: A tiles 2048 16B-units each (256r x 8c), B tiles 1024 (128r x 8c)
    auto load_chunk = [&](int ci) {
        uint32_t buf = sb + (uint32_t)(ci & 1) * 98304;
        int koff = ci * 64;
        #pragma unroll
        for (int it = 0; it < 4; it++) {
            int u = it * 512 + tid;
            int r = u >> 3, c = u & 7;
            size_t go = (size_t)r * K + koff + c * 8;
            cp_async16(buf + sw_off(r, c), Ah_g + go);
            cp_async16(buf + 32768 + sw_off(r, c), Al_g + go);
        }
        #pragma unroll
        for (int it = 0; it < 2; it++) {
            int u = it * 512 + tid;
            int r = u >> 3, c = u & 7;
            size_t go = (size_t)r * K + koff + c * 8;
            cp_async16(buf + 65536 + sw_off(r, c), Bh_g + go);
            cp_async16(buf + 81920 + sw_off(r, c), Bl_g + go);
        }
        asm volatile("cp.async.commit_group;");
    };

    load_chunk(0);

    for (int i = 0; i < nc; i++) {
        if (i + 1 < nc) {
            load_chunk(i + 1);
            asm volatile("cp.async.wait_group 1;");
        } else {
            asm volatile("cp.async.wait_group 0;");
        }
        __syncthreads();

        uint32_t buf = sb + (uint32_t)(i & 1) * 98304;
        #pragma unroll
        for (int s = 0; s < 4; s++) {
            uint32_t ca = (uint32_t)((2 * s + acb) << 4);
            uint32_t cb = (uint32_t)((2 * s + bcb) << 4);
            uint32_t ah[2][4], al[2][4];
            #pragma unroll
            for (int mf = 0; mf < 2; mf++) {
                ldmatrix_x4(ah[mf][0], ah[mf][1], ah[mf][2], ah[mf][3],
                            buf + aPre[mf] + (ca ^ aXr[mf]));
                ldmatrix_x4(al[mf][0], al[mf][1], al[mf][2], al[mf][3],
                            buf + 32768 + aPre[mf] + (ca ^ aXr[mf]));
            }
            uint32_t bh[4][4], bl[4][4];
            #pragma unroll
            for (int p = 0; p < 4; p++) {
                ldmatrix_x4(bh[p][0], bh[p][1], bh[p][2], bh[p][3],
                            buf + 65536 + bPre[p] + (cb ^ bXr[p]));
                ldmatrix_x4(bl[p][0], bl[p][1], bl[p][2], bl[p][3],
                            buf + 81920 + bPre[p] + (cb ^ bXr[p]));
            }
            #pragma unroll
            for (int mf = 0; mf < 2; mf++) {
                #pragma unroll
                for (int p = 0; p < 4; p++) {
                    mma_bf16(acc[mf][2 * p],     ah[mf], bh[p][0], bh[p][1]);
                    mma_bf16(acc[mf][2 * p + 1], ah[mf], bh[p][2], bh[p][3]);
                    mma_bf16(acc[mf][2 * p],     ah[mf], bl[p][0], bl[p][1]);
                    mma_bf16(acc[mf][2 * p + 1], ah[mf], bl[p][2], bl[p][3]);
                    mma_bf16(acc[mf][2 * p],     al[mf], bh[p][0], bh[p][1]);
                    mma_bf16(acc[mf][2 * p + 1], al[mf], bh[p][2], bh[p][3]);
                }
            }
        }
        __syncthreads();
    }

    int qr = lane >> 2, qc = (lane & 3) * 2;
    #pragma unroll
    for (int mf = 0; mf < 2; mf++) {
        #pragma unroll
        for (int half = 0; half < 2; half++) {
            int row = m0 + wm * 32 + mf * 16 + half * 8 + qr;
            #pragma unroll
            for (int nf = 0; nf < 8; nf++) {
                int col = n0 + wn * 64 + nf * 8 + qc;
                float v0 = acc[mf][nf][half * 2 + 0] + bias[col];
                float v1 = acc[mf][nf][half * 2 + 1] + bias[col + 1];
                if (ACT == 1) { v0 = gelu_exact(v0); v1 = gelu_exact(v1); }
                if (ADD) {
                    v0 += addp[(size_t)row * N + col];
                    v1 += addp[(size_t)row * N + col + 1];
                }
                if (OUTF32) {
                    *(float2*)&C[(size_t)row * N + col] = make_float2(v0, v1);
                }
                if (OUTBF16) {
                    __nv_bfloat16 h0, l0, h1, l1;
                    split_bf16(v0, h0, l0);
                    split_bf16(v1, h1, l1);
                    *(uint32_t*)&Chi[(size_t)row * N + col] = pack2(h0, h1);
                    *(uint32_t*)&Clo[(size_t)row * N + col] = pack2(l0, l1);
                }
            }
        }
    }
}

// ---------------------------------------------------------------------------
// Tensor-core flash attention v2: inputs pre-split bf16 (qkvh/qkvl),
// cp.async loads, double-buffered K/V stages. 128 q x one (b,h), 256 thr.
// Smem: Qh|Ql (32KB) + 2 stages x (Kh|Kl|Vh|Vl = 64KB) = 160KB.
// ---------------------------------------------------------------------------
#define TATTN_SMEM (32768 + 2 * 65536)   // 163840

__global__ void __launch_bounds__(256, 1)
tattn_kernel(const __nv_bfloat16* __restrict__ qkvh,
             const __nv_bfloat16* __restrict__ qkvl,
             __nv_bfloat16* __restrict__ oh,
             __nv_bfloat16* __restrict__ ol) {
    extern __shared__ char smc[];
    uint32_t sb = smem_u32(smc);

    int qt = blockIdx.x;              // 0..7
    int bh = blockIdx.y;              // 0..95
    int b = bh / HEADS, h = bh % HEADS;
    int tid = threadIdx.x, wid = tid >> 5, lane = tid & 31;
    int g = lane >> 3, lr = lane & 7;

    size_t tokb = (size_t)b * SEQ;

    // --- Q tiles (hi, lo) via cp.async ---
    #pragma unroll
    for (int it = 0; it < 4; it++) {
        int u = it * 256 + tid;
        int r = u >> 3, c = u & 7;
        size_t go = (tokb + qt * 128 + r) * QKVD + h * HD + c * 8;
        cp_async16(sb + sw_off(r, c), qkvh + go);
        cp_async16(sb + 16384 + sw_off(r, c), qkvl + go);
    }
    asm volatile("cp.async.commit_group;");

    auto load_kv = [&](int kt) {
        uint32_t stg = sb + 32768 + (uint32_t)(kt & 1) * 65536;
        #pragma unroll
        for (int it = 0; it < 4; it++) {
            int u = it * 256 + tid;
            int r = u >> 3, c = u & 7;
            size_t go = (tokb + kt * 128 + r) * QKVD + h * HD + c * 8;
            cp_async16(stg + sw_off(r, c),         qkvh + go + DIM);
            cp_async16(stg + 16384 + sw_off(r, c), qkvl + go + DIM);
            cp_async16(stg + 32768 + sw_off(r, c), qkvh + go + 2 * DIM);
            cp_async16(stg + 49152 + sw_off(r, c), qkvl + go + 2 * DIM);
        }
        asm volatile("cp.async.commit_group;");
    };

    load_kv(0);
    asm volatile("cp.async.wait_group 1;");   // Q ready
    __syncthreads();

    // --- hoist Q fragments ---
    uint32_t qh[4][4], ql[4][4];
    {
        int arow = wid * 16 + (g & 1) * 8 + lr;
        uint32_t aOff = (uint32_t)(arow * 128), aX = (uint32_t)((arow & 7) << 4);
        #pragma unroll
        for (int s = 0; s < 4; s++) {
            uint32_t ca = (uint32_t)((2 * s + (g >> 1)) << 4);
            ldmatrix_x4(qh[s][0], qh[s][1], qh[s][2], qh[s][3], sb + aOff + (ca ^ aX));
            ldmatrix_x4(ql[s][0], ql[s][1], ql[s][2], ql[s][3], sb + 16384 + aOff + (ca ^ aX));
        }
    }

    float m0 = -1e30f, m1 = -1e30f, l0 = 0.0f, l1 = 0.0f;
    float O[8][4];
    #pragma unroll
    for (int j = 0; j < 8; j++)
        #pragma unroll
        for (int q = 0; q < 4; q++) O[j][q] = 0.0f;

    for (int kt = 0; kt < 8; kt++) {
        if (kt + 1 < 8) {
            load_kv(kt + 1);
            asm volatile("cp.async.wait_group 1;");
        } else {
            asm volatile("cp.async.wait_group 0;");
        }
        __syncthreads();

        uint32_t stg = sb + 32768 + (uint32_t)(kt & 1) * 65536;

        // --- S = Q @ K^T (16 n8 frags), 3-term split ---
        float S[16][4];
        #pragma unroll
        for (int nf = 0; nf < 16; nf++)
            #pragma unroll
            for (int q = 0; q < 4; q++) S[nf][q] = 0.0f;

        #pragma unroll
        for (int s = 0; s < 4; s++) {
            #pragma unroll
            for (int p = 0; p < 8; p++) {
                int brow = p * 16 + (g >> 1) * 8 + lr;
                uint32_t bOff = (uint32_t)(brow * 128), bX = (uint32_t)((brow & 7) << 4);
                uint32_t cb = (uint32_t)((2 * s + (g & 1)) << 4);
                uint32_t kh[4], kl[4];
                ldmatrix_x4(kh[0], kh[1], kh[2], kh[3], stg + bOff + (cb ^ bX));
                ldmatrix_x4(kl[0], kl[1], kl[2], kl[3], stg + 16384 + bOff + (cb ^ bX));
                mma_bf16(S[2 * p],     qh[s], kh[0], kh[1]);
                mma_bf16(S[2 * p + 1], qh[s], kh[2], kh[3]);
                mma_bf16(S[2 * p],     qh[s], kl[0], kl[1]);
                mma_bf16(S[2 * p + 1], qh[s], kl[2], kl[3]);
                mma_bf16(S[2 * p],     ql[s], kh[0], kh[1]);
                mma_bf16(S[2 * p + 1], ql[s], kh[2], kh[3]);
            }
        }

        // apply softmax scale (1/8, exact)
        #pragma unroll
        for (int nf = 0; nf < 16; nf++) {
            S[nf][0] *= 0.125f; S[nf][1] *= 0.125f;
            S[nf][2] *= 0.125f; S[nf][3] *= 0.125f;
        }

        // --- online softmax ---
        float mt0 = -1e30f, mt1 = -1e30f;
        #pragma unroll
        for (int nf = 0; nf < 16; nf++) {
            mt0 = fmaxf(mt0, fmaxf(S[nf][0], S[nf][1]));
            mt1 = fmaxf(mt1, fmaxf(S[nf][2], S[nf][3]));
        }
        mt0 = fmaxf(mt0, __shfl_xor_sync(0xffffffffu, mt0, 1));
        mt0 = fmaxf(mt0, __shfl_xor_sync(0xffffffffu, mt0, 2));
        mt1 = fmaxf(mt1, __shfl_xor_sync(0xffffffffu, mt1, 1));
        mt1 = fmaxf(mt1, __shfl_xor_sync(0xffffffffu, mt1, 2));
        float mn0 = fmaxf(m0, mt0), mn1 = fmaxf(m1, mt1);
        float c0 = __expf(m0 - mn0), c1 = __expf(m1 - mn1);
        m0 = mn0; m1 = mn1;
        #pragma unroll
        for (int j = 0; j < 8; j++) {
            O[j][0] *= c0; O[j][1] *= c0;
            O[j][2] *= c1; O[j][3] *= c1;
        }
        float s0 = 0.0f, s1 = 0.0f;
        #pragma unroll
        for (int nf = 0; nf < 16; nf++) {
            S[nf][0] = __expf(S[nf][0] - mn0); s0 += S[nf][0];
            S[nf][1] = __expf(S[nf][1] - mn0); s0 += S[nf][1];
            S[nf][2] = __expf(S[nf][2] - mn1); s1 += S[nf][2];
            S[nf][3] = __expf(S[nf][3] - mn1); s1 += S[nf][3];
        }
        s0 += __shfl_xor_sync(0xffffffffu, s0, 1);
        s0 += __shfl_xor_sync(0xffffffffu, s0, 2);
        s1 += __shfl_xor_sync(0xffffffffu, s1, 1);
        s1 += __shfl_xor_sync(0xffffffffu, s1, 2);
        l0 = l0 * c0 + s0;
        l1 = l1 * c1 + s1;

        // --- O += P @ V, P frags from S accumulators, 3-term ---
        #pragma unroll
        for (int s = 0; s < 8; s++) {
            uint32_t ph[4], pl[4];
            #pragma unroll
            for (int q = 0; q < 2; q++) {
                float x0 = S[2 * s + q][0], x1 = S[2 * s + q][1];
                float x2 = S[2 * s + q][2], x3 = S[2 * s + q][3];
                __nv_bfloat16 hx0 = __float2bfloat16(x0), hx1 = __float2bfloat16(x1);
                __nv_bfloat16 hx2 = __float2bfloat16(x2), hx3 = __float2bfloat16(x3);
                ph[2 * q + 0] = pack2(hx0, hx1);
                ph[2 * q + 1] = pack2(hx2, hx3);
                pl[2 * q + 0] = pack2(__float2bfloat16(x0 - __bfloat162float(hx0)),
                                      __float2bfloat16(x1 - __bfloat162float(hx1)));
                pl[2 * q + 1] = pack2(__float2bfloat16(x2 - __bfloat162float(hx2)),
                                      __float2bfloat16(x3 - __bfloat162float(hx3)));
            }
            int krow = s * 16 + (g & 1) * 8 + lr;
            uint32_t vOff = (uint32_t)(krow * 128), vX = (uint32_t)((krow & 7) << 4);
            #pragma unroll
            for (int t = 0; t < 4; t++) {
                uint32_t cv = (uint32_t)((2 * t + (g >> 1)) << 4);
                uint32_t vh[4], vl[4];
                ldmatrix_x4t(vh[0], vh[1], vh[2], vh[3], stg + 32768 + vOff + (cv ^ vX));
                ldmatrix_x4t(vl[0], vl[1], vl[2], vl[3], stg + 49152 + vOff + (cv ^ vX));
                mma_bf16(O[2 * t],     ph, vh[0], vh[1]);
                mma_bf16(O[2 * t + 1], ph, vh[2], vh[3]);
                mma_bf16(O[2 * t],     ph, vl[0], vl[1]);
                mma_bf16(O[2 * t + 1], ph, vl[2], vl[3]);
                mma_bf16(O[2 * t],     pl, vh[0], vh[1]);
                mma_bf16(O[2 * t + 1], pl, vh[2], vh[3]);
            }
        }
        __syncthreads();
    }

    // --- epilogue ---
    float inv0 = 1.0f / l0, inv1 = 1.0f / l1;
    int r0 = qt * 128 + wid * 16 + (lane >> 2);
    int colb = h * HD + (lane & 3) * 2;
    #pragma unroll
    for (int j = 0; j < 8; j++) {
        int col = colb + j * 8;
        float v0 = O[j][0] * inv0, v1 = O[j][1] * inv0;
        float v2 = O[j][2] * inv1, v3 = O[j][3] * inv1;
        __nv_bfloat16 h0, lo0, h1, lo1;
        split_bf16(v0, h0, lo0); split_bf16(v1, h1, lo1);
        size_t ob0 = (tokb + r0) * DIM + col;
        *(uint32_t*)&oh[ob0] = pack2(h0, h1);
        *(uint32_t*)&ol[ob0] = pack2(lo0, lo1);
        split_bf16(v2, h0, lo0); split_bf16(v3, h1, lo1);
        size_t ob1 = (tokb + r0 + 8) * DIM + col;
        *(uint32_t*)&oh[ob1] = pack2(h0, h1);
        *(uint32_t*)&ol[ob1] = pack2(lo0, lo1);
    }
}

// ---------------------------------------------------------------------------
// Launch
// ---------------------------------------------------------------------------
extern "C" void kernel_launch(void* const* d_in, const int* in_sizes, int n_in,
                              void* d_out, int out_size) {
    const float* x       = (const float*)d_in[0];
    const float* ln1_g   = (const float*)d_in[1];
    const float* ln1_b   = (const float*)d_in[2];
    const float* qkv_w   = (const float*)d_in[3];
    const float* qkv_b   = (const float*)d_in[4];
    const float* proj_w  = (const float*)d_in[5];
    const float* proj_b  = (const float*)d_in[6];
    const float* c_qkv_w = (const float*)d_in[7];
    const float* c_qkv_b = (const float*)d_in[8];
    const float* c_proj_w= (const float*)d_in[9];
    const float* c_proj_b= (const float*)d_in[10];
    const float* cp_fc1_w= (const float*)d_in[11];
    const float* cp_fc1_b= (const float*)d_in[12];
    const float* cp_fc2_w= (const float*)d_in[13];
    const float* cp_fc2_b= (const float*)d_in[14];
    const float* P       = (const float*)d_in[15];
    const float* ln2_g   = (const float*)d_in[16];
    const float* ln2_b   = (const float*)d_in[17];
    const float* fc1_w   = (const float*)d_in[18];
    const float* fc1_b   = (const float*)d_in[19];
    const float* fc2_w   = (const float*)d_in[20];
    const float* fc2_b   = (const float*)d_in[21];

    float *n1, *rinv, *pn, *y, *z, *dmap, *cph, *xsum;
    __nv_bfloat16 *qkvh, *qkvl;
    __nv_bfloat16 *n1h, *n1l, *aoh, *aol, *zinh, *zinl, *n2h, *n2l, *hh, *hl;
    __nv_bfloat16 *wqkvh, *wqkvl, *wprojh, *wprojl, *wcqkvh, *wcqkvl, *wcprojh, *wcprojl;
    __nv_bfloat16 *wfc1h, *wfc1l, *wfc2h, *wfc2l;

    cudaGetSymbolAddress((void**)&n1,    g_n1);
    cudaGetSymbolAddress((void**)&rinv,  g_rinv);
    cudaGetSymbolAddress((void**)&pn,    g_pn);
    cudaGetSymbolAddress((void**)&qkvh,  g_qkvh);
    cudaGetSymbolAddress((void**)&qkvl,  g_qkvl);
    cudaGetSymbolAddress((void**)&y,     g_y);
    cudaGetSymbolAddress((void**)&z,     g_z);
    cudaGetSymbolAddress((void**)&dmap,  g_dmap);
    cudaGetSymbolAddress((void**)&cph,   g_cph);
    cudaGetSymbolAddress((void**)&xsum,  g_xsum);
    cudaGetSymbolAddress((void**)&n1h,   g_n1h);
    cudaGetSymbolAddress((void**)&n1l,   g_n1l);
    cudaGetSymbolAddress((void**)&aoh,   g_aoh);
    cudaGetSymbolAddress((void**)&aol,   g_aol);
    cudaGetSymbolAddress((void**)&zinh,  g_zinh);
    cudaGetSymbolAddress((void**)&zinl,  g_zinl);
    cudaGetSymbolAddress((void**)&n2h,   g_n2h);
    cudaGetSymbolAddress((void**)&n2l,   g_n2l);
    cudaGetSymbolAddress((void**)&hh,    g_hh);
    cudaGetSymbolAddress((void**)&hl,    g_hl);
    cudaGetSymbolAddress((void**)&wqkvh, g_wqkvh);
    cudaGetSymbolAddress((void**)&wqkvl, g_wqkvl);
    cudaGetSymbolAddress((void**)&wprojh, g_wprojh);
    cudaGetSymbolAddress((void**)&wprojl, g_wprojl);
    cudaGetSymbolAddress((void**)&wcqkvh, g_wcqkvh);
    cudaGetSymbolAddress((void**)&wcqkvl, g_wcqkvl);
    cudaGetSymbolAddress((void**)&wcprojh, g_wcprojh);
    cudaGetSymbolAddress((void**)&wcprojl, g_wcprojl);
    cudaGetSymbolAddress((void**)&wfc1h, g_wfc1h);
    cudaGetSymbolAddress((void**)&wfc1l, g_wfc1l);
    cudaGetSymbolAddress((void**)&wfc2h, g_wfc2h);
    cudaGetSymbolAddress((void**)&wfc2l, g_wfc2l);

    cudaFuncSetAttribute(tattn_kernel, cudaFuncAttributeMaxDynamicSharedMemorySize, TATTN_SMEM);
    cudaFuncSetAttribute(hgemm<0, false, false, true >, cudaFuncAttributeMaxDynamicSharedMemorySize, HG_SMEM);
    cudaFuncSetAttribute(hgemm<0, false, true,  false>, cudaFuncAttributeMaxDynamicSharedMemorySize, HG_SMEM);
    cudaFuncSetAttribute(hgemm<1, false, false, true >, cudaFuncAttributeMaxDynamicSharedMemorySize, HG_SMEM);
    cudaFuncSetAttribute(hgemm<0, true,  true,  false>, cudaFuncAttributeMaxDynamicSharedMemorySize, HG_SMEM);

    float* out_x = (float*)d_out;

    // 0) weight conversion fp32 -> bf16 hi/lo (vectorized x4)
    cvt_kernel<<<(QKVD * DIM / 4 + 255) / 256, 256>>>(qkv_w,   wqkvh,  wqkvl,  QKVD * DIM / 4);
    cvt_kernel<<<(DIM * DIM  / 4 + 255) / 256, 256>>>(proj_w,  wprojh, wprojl, DIM * DIM / 4);
    cvt_kernel<<<(QKVD * DIM / 4 + 255) / 256, 256>>>(c_qkv_w, wcqkvh, wcqkvl, QKVD * DIM / 4);
    cvt_kernel<<<(DIM * DIM  / 4 + 255) / 256, 256>>>(c_proj_w,wcprojh,wcprojl,DIM * DIM / 4);
    cvt_kernel<<<(MLPH * DIM / 4 + 255) / 256, 256>>>(fc1_w,   wfc1h,  wfc1l,  MLPH * DIM / 4);
    cvt_kernel<<<(DIM * MLPH / 4 + 255) / 256, 256>>>(fc2_w,   wfc2h,  wfc2l,  DIM * MLPH / 4);

    // 1) LN1 (+ norms) and Pn
    ln_kernel<<<TOK, 256>>>(x, ln1_g, ln1_b, n1, n1h, n1l, rinv);
    pn_kernel<<<KP, 256>>>(P, pn);

    // 2) branch 1 attention (qkv written as split-bf16)
    hgemm<0, false, false, true><<<dim3(QKVD / 128, TOK / 256), 512, HG_SMEM>>>(
        n1h, n1l, wqkvh, wqkvl, qkv_b, nullptr, nullptr, qkvh, qkvl, TOK, QKVD, DIM);
    tattn_kernel<<<dim3(SEQ / 128, BATCH * HEADS), 256, TATTN_SMEM>>>(qkvh, qkvl, aoh, aol);
    hgemm<0, false, true, false><<<dim3(DIM / 128, TOK / 256), 512, HG_SMEM>>>(
        aoh, aol, wprojh, wprojl, proj_b, nullptr, y, nullptr, nullptr, TOK, DIM, DIM);

    // 3) similarity map + c_project MLP (fp32)
    sgemm64<0, false, true, false><<<dim3(KP / 64, TOK / 64), 256>>>(
        n1, pn, nullptr, rinv, dmap, nullptr, nullptr, TOK, KP, DIM);
    sgemm64<1, true, false, false><<<dim3(KP / 64, TOK / 64), 256>>>(
        dmap, cp_fc1_w, cp_fc1_b, nullptr, cph, nullptr, nullptr, TOK, KP, KP);
    sgemm64<0, true, false, true><<<dim3(DIM / 64, TOK / 64), 256>>>(
        cph, cp_fc2_w, cp_fc2_b, nullptr, nullptr, zinh, zinl, TOK, DIM, KP);

    // 4) branch 2 attention
    hgemm<0, false, false, true><<<dim3(QKVD / 128, TOK / 256), 512, HG_SMEM>>>(
        zinh, zinl, wcqkvh, wcqkvl, c_qkv_b, nullptr, nullptr, qkvh, qkvl, TOK, QKVD, DIM);
    tattn_kernel<<<dim3(SEQ / 128, BATCH * HEADS), 256, TATTN_SMEM>>>(qkvh, qkvl, aoh, aol);
    hgemm<0, false, true, false><<<dim3(DIM / 128, TOK / 256), 512, HG_SMEM>>>(
        aoh, aol, wcprojh, wcprojl, c_proj_b, nullptr, z, nullptr, nullptr, TOK, DIM, DIM);

    // 5) residual sum + LN2
    addln_kernel<<<TOK, 256>>>(x, y, z, ln2_g, ln2_b, xsum, n2h, n2l);

    // 6) MLP (tensor)
    hgemm<1, false, false, true><<<dim3(MLPH / 128, TOK / 256), 512, HG_SMEM>>>(
        n2h, n2l, wfc1h, wfc1l, fc1_b, nullptr, nullptr, hh, hl, TOK, MLPH, DIM);
    hgemm<0, true, true, false><<<dim3(DIM / 128, TOK / 256), 512, HG_SMEM>>>(
        hh, hl, wfc2h, wfc2l, fc2_b, xsum, out_x, nullptr, nullptr, TOK, DIM, MLPH);

    // 7) dmap output
    if (out_size >= TOK * DIM + TOK * KP) {
        cudaMemcpyAsync(out_x + (size_t)TOK * DIM, dmap,
                        (size_t)TOK * KP * sizeof(float),
                        cudaMemcpyDeviceToDevice);
    }
}

// round 9
// speedup vs baseline: 1.0862x; 1.0862x over previous
#include <cuda_runtime.h>
#include <cuda_bf16.h>
#include <math.h>
#include <stdint.h>

// ---------------------------------------------------------------------------
// Problem constants
// ---------------------------------------------------------------------------
#define BATCH 8
#define SEQ   1024
#define TOK   (BATCH * SEQ)        // 8192 tokens
#define DIM   768
#define HEADS 12
#define HD    64
#define KP    64
#define MLPH  3072
#define QKVD  (3 * DIM)            // 2304
#define LN_EPS 1e-5f

// ---------------------------------------------------------------------------
// Scratch (device globals; no allocations allowed)
// ---------------------------------------------------------------------------
__device__ __align__(256) float g_n1  [TOK * DIM];
__device__ __align__(256) float g_rinv[TOK];
__device__ __align__(256) float g_pn  [KP * DIM];
__device__ __align__(256) float g_y   [TOK * DIM];
__device__ __align__(256) float g_z   [TOK * DIM];
__device__ __align__(256) float g_dmap[TOK * KP];
__device__ __align__(256) float g_cph [TOK * KP];
__device__ __align__(256) float g_xsum[TOK * DIM];

__device__ __align__(256) __nv_bfloat16 g_qkvh[TOK * QKVD];
__device__ __align__(256) __nv_bfloat16 g_qkvl[TOK * QKVD];

__device__ __align__(256) __nv_bfloat16 g_n1h [TOK * DIM];
__device__ __align__(256) __nv_bfloat16 g_n1l [TOK * DIM];
__device__ __align__(256) __nv_bfloat16 g_aoh [TOK * DIM];
__device__ __align__(256) __nv_bfloat16 g_aol [TOK * DIM];
__device__ __align__(256) __nv_bfloat16 g_zinh[TOK * DIM];
__device__ __align__(256) __nv_bfloat16 g_zinl[TOK * DIM];
__device__ __align__(256) __nv_bfloat16 g_n2h [TOK * DIM];
__device__ __align__(256) __nv_bfloat16 g_n2l [TOK * DIM];
__device__ __align__(256) __nv_bfloat16 g_hh  [TOK * MLPH];
__device__ __align__(256) __nv_bfloat16 g_hl  [TOK * MLPH];

__device__ __align__(256) __nv_bfloat16 g_wqkvh [QKVD * DIM];
__device__ __align__(256) __nv_bfloat16 g_wqkvl [QKVD * DIM];
__device__ __align__(256) __nv_bfloat16 g_wprojh[DIM * DIM];
__device__ __align__(256) __nv_bfloat16 g_wprojl[DIM * DIM];
__device__ __align__(256) __nv_bfloat16 g_wcqkvh[QKVD * DIM];
__device__ __align__(256) __nv_bfloat16 g_wcqkvl[QKVD * DIM];
__device__ __align__(256) __nv_bfloat16 g_wcprojh[DIM * DIM];
__device__ __align__(256) __nv_bfloat16 g_wcprojl[DIM * DIM];
__device__ __align__(256) __nv_bfloat16 g_wfc1h[MLPH * DIM];
__device__ __align__(256) __nv_bfloat16 g_wfc1l[MLPH * DIM];
__device__ __align__(256) __nv_bfloat16 g_wfc2h[DIM * MLPH];
__device__ __align__(256) __nv_bfloat16 g_wfc2l[DIM * MLPH];

// ---------------------------------------------------------------------------
// Helpers
// ---------------------------------------------------------------------------
__device__ __forceinline__ float gelu_exact(float v) {
    return 0.5f * v * (1.0f + erff(v * 0.70710678118654752f));
}

__device__ __forceinline__ void split_bf16(float v, __nv_bfloat16& hi, __nv_bfloat16& lo) {
    hi = __float2bfloat16(v);
    lo = __float2bfloat16(v - __bfloat162float(hi));
}

__device__ __forceinline__ uint32_t pack2(__nv_bfloat16 lo, __nv_bfloat16 hi) {
    __nv_bfloat162 t;
    t.x = lo; t.y = hi;
    return *(uint32_t*)&t;
}

__device__ __forceinline__ float block_sum256(float v, float* red) {
    int tid = threadIdx.x;
    red[tid] = v;
    __syncthreads();
    #pragma unroll
    for (int s = 128; s > 0; s >>= 1) {
        if (tid < s) red[tid] += red[tid + s];
        __syncthreads();
    }
    float r = red[0];
    __syncthreads();
    return r;
}

__device__ __forceinline__ uint32_t smem_u32(const void* p) {
    uint32_t a;
    asm("{ .reg .u64 t; cvta.to.shared.u64 t, %1; cvt.u32.u64 %0, t; }" : "=r"(a) : "l"(p));
    return a;
}

__device__ __forceinline__ void cp_async16(uint32_t dst, const void* src) {
    asm volatile("cp.async.cg.shared.global [%0], [%1], 16;" :: "r"(dst), "l"(src));
}

__device__ __forceinline__ void ldmatrix_x4(uint32_t& r0, uint32_t& r1,
                                            uint32_t& r2, uint32_t& r3, uint32_t addr) {
    asm volatile("ldmatrix.sync.aligned.m8n8.x4.shared.b16 {%0,%1,%2,%3}, [%4];"
                 : "=r"(r0), "=r"(r1), "=r"(r2), "=r"(r3) : "r"(addr));
}

__device__ __forceinline__ void ldmatrix_x4t(uint32_t& r0, uint32_t& r1,
                                             uint32_t& r2, uint32_t& r3, uint32_t addr) {
    asm volatile("ldmatrix.sync.aligned.m8n8.x4.trans.shared.b16 {%0,%1,%2,%3}, [%4];"
                 : "=r"(r0), "=r"(r1), "=r"(r2), "=r"(r3) : "r"(addr));
}

__device__ __forceinline__ void mma_bf16(float* d, const uint32_t* a, uint32_t b0, uint32_t b1) {
    asm volatile(
        "mma.sync.aligned.m16n8k16.row.col.f32.bf16.bf16.f32 "
        "{%0,%1,%2,%3}, {%4,%5,%6,%7}, {%8,%9}, {%0,%1,%2,%3};"
        : "+f"(d[0]), "+f"(d[1]), "+f"(d[2]), "+f"(d[3])
        : "r"(a[0]), "r"(a[1]), "r"(a[2]), "r"(a[3]), "r"(b0), "r"(b1));
}

// swizzled offset inside a 128-byte-row tile, 16-byte granularity
__device__ __forceinline__ uint32_t sw_off(int r, int c16) {
    return (uint32_t)(r * 128 + ((c16 * 16) ^ ((r & 7) << 4)));
}

// ---------------------------------------------------------------------------
// Elementwise kernels
// ---------------------------------------------------------------------------
__global__ void cvt_kernel(const float* __restrict__ w,
                           __nv_bfloat16* __restrict__ hi,
                           __nv_bfloat16* __restrict__ lo, int n4) {
    int i = blockIdx.x * blockDim.x + threadIdx.x;
    if (i < n4) {
        float4 v = *(const float4*)(w + i * 4);
        __nv_bfloat16 h0, l0, h1, l1, h2, l2, h3, l3;
        split_bf16(v.x, h0, l0); split_bf16(v.y, h1, l1);
        split_bf16(v.z, h2, l2); split_bf16(v.w, h3, l3);
        *(uint2*)(hi + i * 4) = make_uint2(pack2(h0, h1), pack2(h2, h3));
        *(uint2*)(lo + i * 4) = make_uint2(pack2(l0, l1), pack2(l2, l3));
    }
}

__global__ void ln_kernel(const float* __restrict__ x,
                          const float* __restrict__ g,
                          const float* __restrict__ b,
                          float* __restrict__ out,
                          __nv_bfloat16* __restrict__ ohi,
                          __nv_bfloat16* __restrict__ olo,
                          float* __restrict__ rinv) {
    __shared__ float red[256];
    int row = blockIdx.x;
    int tid = threadIdx.x;
    size_t base = (size_t)row * DIM;

    float v0 = x[base + tid];
    float v1 = x[base + 256 + tid];
    float v2 = x[base + 512 + tid];

    float mu = block_sum256(v0 + v1 + v2, red) * (1.0f / DIM);
    float d0 = v0 - mu, d1 = v1 - mu, d2 = v2 - mu;
    float var = block_sum256(d0 * d0 + d1 * d1 + d2 * d2, red) * (1.0f / DIM);
    float inv = rsqrtf(var + LN_EPS);

    float t0 = d0 * inv * g[tid]       + b[tid];
    float t1 = d1 * inv * g[tid + 256] + b[tid + 256];
    float t2 = d2 * inv * g[tid + 512] + b[tid + 512];
    out[base + tid] = t0; out[base + 256 + tid] = t1; out[base + 512 + tid] = t2;

    __nv_bfloat16 h, l;
    split_bf16(t0, h, l); ohi[base + tid] = h;       olo[base + tid] = l;
    split_bf16(t1, h, l); ohi[base + 256 + tid] = h; olo[base + 256 + tid] = l;
    split_bf16(t2, h, l); ohi[base + 512 + tid] = h; olo[base + 512 + tid] = l;

    float s2 = block_sum256(t0 * t0 + t1 * t1 + t2 * t2, red);
    if (tid == 0) rinv[row] = rsqrtf(s2);
}

__global__ void addln_kernel(const float* __restrict__ x,
                             const float* __restrict__ y,
                             const float* __restrict__ z,
                             const float* __restrict__ g,
                             const float* __restrict__ b,
                             float* __restrict__ xsum,
                             __nv_bfloat16* __restrict__ n2h,
                             __nv_bfloat16* __restrict__ n2l) {
    __shared__ float red[256];
    int row = blockIdx.x;
    int tid = threadIdx.x;
    size_t base = (size_t)row * DIM;

    float v0 = x[base + tid]       + y[base + tid]       + z[base + tid];
    float v1 = x[base + 256 + tid] + y[base + 256 + tid] + z[base + 256 + tid];
    float v2 = x[base + 512 + tid] + y[base + 512 + tid] + z[base + 512 + tid];
    xsum[base + tid] = v0; xsum[base + 256 + tid] = v1; xsum[base + 512 + tid] = v2;

    float mu = block_sum256(v0 + v1 + v2, red) * (1.0f / DIM);
    float d0 = v0 - mu, d1 = v1 - mu, d2 = v2 - mu;
    float var = block_sum256(d0 * d0 + d1 * d1 + d2 * d2, red) * (1.0f / DIM);
    float inv = rsqrtf(var + LN_EPS);

    float t0 = d0 * inv * g[tid]       + b[tid];
    float t1 = d1 * inv * g[tid + 256] + b[tid + 256];
    float t2 = d2 * inv * g[tid + 512] + b[tid + 512];

    __nv_bfloat16 h, l;
    split_bf16(t0, h, l); n2h[base + tid] = h;       n2l[base + tid] = l;
    split_bf16(t1, h, l); n2h[base + 256 + tid] = h; n2l[base + 256 + tid] = l;
    split_bf16(t2, h, l); n2h[base + 512 + tid] = h; n2l[base + 512 + tid] = l;
}

__global__ void pn_kernel(const float* __restrict__ P, float* __restrict__ pn) {
    __shared__ float red[256];
    int row = blockIdx.x;
    int tid = threadIdx.x;
    size_t base = (size_t)row * DIM;
    float v0 = P[base + tid], v1 = P[base + 256 + tid], v2 = P[base + 512 + tid];
    float s2 = block_sum256(v0 * v0 + v1 * v1 + v2 * v2, red);
    float inv = rsqrtf(s2);
    pn[base + tid] = v0 * inv;
    pn[base + 256 + tid] = v1 * inv;
    pn[base + 512 + tid] = v2 * inv;
}

// ---------------------------------------------------------------------------
// fp32 SGEMM for small GEMMs: C[M,N] = A[M,K] @ B[N,K]^T
// ---------------------------------------------------------------------------
template <int ACT, bool BIAS, bool RSCALE, bool BF16OUT>
__global__ void sgemm64(const float* __restrict__ A,
                        const float* __restrict__ B,
                        const float* __restrict__ bias,
                        const float* __restrict__ rs,
                        float* __restrict__ C,
                        __nv_bfloat16* __restrict__ Chi,
                        __nv_bfloat16* __restrict__ Clo,
                        int M, int N, int K) {
    __shared__ float As[16][65];
    __shared__ float Bs[16][65];

    int tid = threadIdx.x;
    int m0 = blockIdx.y * 64;
    int n0 = blockIdx.x * 64;
    int ty = tid >> 4, tx = tid & 15;
    int lrow = tid >> 2;
    int lk   = (tid & 3) * 4;

    const float* Ap = A + (size_t)(m0 + lrow) * K + lk;
    const float* Bp = B + (size_t)(n0 + lrow) * K + lk;

    float acc[4][4];
    #pragma unroll
    for (int i = 0; i < 4; i++)
        #pragma unroll
        for (int j = 0; j < 4; j++) acc[i][j] = 0.0f;

    for (int k0 = 0; k0 < K; k0 += 16) {
        float4 av = *(const float4*)(Ap + k0);
        float4 bv = *(const float4*)(Bp + k0);
        As[lk + 0][lrow] = av.x; As[lk + 1][lrow] = av.y;
        As[lk + 2][lrow] = av.z; As[lk + 3][lrow] = av.w;
        Bs[lk + 0][lrow] = bv.x; Bs[lk + 1][lrow] = bv.y;
        Bs[lk + 2][lrow] = bv.z; Bs[lk + 3][lrow] = bv.w;
        __syncthreads();

        #pragma unroll
        for (int kk = 0; kk < 16; kk++) {
            float a[4], bb[4];
            #pragma unroll
            for (int i = 0; i < 4; i++) a[i]  = As[kk][ty * 4 + i];
            #pragma unroll
            for (int j = 0; j < 4; j++) bb[j] = Bs[kk][tx * 4 + j];
            #pragma unroll
            for (int i = 0; i < 4; i++)
                #pragma unroll
                for (int j = 0; j < 4; j++)
                    acc[i][j] = fmaf(a[i], bb[j], acc[i][j]);
        }
        __syncthreads();
    }

    #pragma unroll
    for (int i = 0; i < 4; i++) {
        int row = m0 + ty * 4 + i;
        float rsv = RSCALE ? rs[row] : 1.0f;
        #pragma unroll
        for (int j = 0; j < 4; j++) {
            int col = n0 + tx * 4 + j;
            float v = acc[i][j];
            if (BIAS) v += bias[col];
            if (ACT == 1) v = gelu_exact(v);
            if (RSCALE) v *= rsv;
            if (BF16OUT) {
                __nv_bfloat16 h, l;
                split_bf16(v, h, l);
                Chi[(size_t)row * N + col] = h;
                Clo[(size_t)row * N + col] = l;
            } else {
                C[(size_t)row * N + col] = v;
            }
        }
    }
}

// ---------------------------------------------------------------------------
// HMMA split-bf16 GEMM (validated R7 config): 128x128 tile, 256 threads,
// K-chunk 64 bf16 (SW128), cp.async double buffer (128KB smem).
// ---------------------------------------------------------------------------
#define HG_SMEM (2 * 4 * 16384)   // 131072

template <int ACT, bool ADD, bool OUTF32, bool OUTBF16>
__global__ void __launch_bounds__(256, 1)
hgemm(const __nv_bfloat16* __restrict__ Ah, const __nv_bfloat16* __restrict__ Al,
      const __nv_bfloat16* __restrict__ Bh, const __nv_bfloat16* __restrict__ Bl,
      const float* __restrict__ bias, const float* __restrict__ addp,
      float* __restrict__ C,
      __nv_bfloat16* __restrict__ Chi, __nv_bfloat16* __restrict__ Clo,
      int M, int N, int K) {
    extern __shared__ char smem[];
    uint32_t sb = smem_u32(smem);

    int tid = threadIdx.x;
    int wid = tid >> 5, lane = tid & 31;
    int wm = wid >> 1, wn = wid & 1;
    int g = lane >> 3, lr = lane & 7;

    int m0 = blockIdx.y * 128, n0 = blockIdx.x * 128;
    int nc = K >> 6;

    uint32_t aPre[2], aXr[2];
    #pragma unroll
    for (int mf = 0; mf < 2; mf++) {
        int r = wm * 32 + mf * 16 + (g & 1) * 8 + lr;
        aPre[mf] = (uint32_t)(r * 128);
        aXr[mf]  = (uint32_t)((r & 7) << 4);
    }
    int acb = g >> 1;
    uint32_t bPre[4], bXr[4];
    #pragma unroll
    for (int p = 0; p < 4; p++) {
        int r = wn * 64 + p * 16 + (g >> 1) * 8 + lr;
        bPre[p] = (uint32_t)(r * 128);
        bXr[p]  = (uint32_t)((r & 7) << 4);
    }
    int bcb = g & 1;

    const __nv_bfloat16* srcs[4] = {
        Ah + (size_t)m0 * K, Al + (size_t)m0 * K,
        Bh + (size_t)n0 * K, Bl + (size_t)n0 * K };

    float acc[2][8][4];
    #pragma unroll
    for (int mf = 0; mf < 2; mf++)
        #pragma unroll
        for (int nf = 0; nf < 8; nf++)
            #pragma unroll
            for (int q = 0; q < 4; q++) acc[mf][nf][q] = 0.0f;

    {
        uint32_t buf = sb;
        #pragma unroll
        for (int it = 0; it < 16; it++) {
            int idx = it * 256 + tid;
            int t = idx >> 10, u = idx & 1023;
            int r = u >> 3, c16 = u & 7;
            cp_async16(buf + t * 16384 + sw_off(r, c16),
                       srcs[t] + (size_t)r * K + c16 * 8);
        }
        asm volatile("cp.async.commit_group;");
    }

    for (int i = 0; i < nc; i++) {
        if (i + 1 < nc) {
            uint32_t buf = sb + (uint32_t)((i + 1) & 1) * 65536;
            #pragma unroll
            for (int it = 0; it < 16; it++) {
                int idx = it * 256 + tid;
                int t = idx >> 10, u = idx & 1023;
                int r = u >> 3, c16 = u & 7;
                cp_async16(buf + t * 16384 + sw_off(r, c16),
                           srcs[t] + (size_t)r * K + (i + 1) * 64 + c16 * 8);
            }
            asm volatile("cp.async.commit_group;");
            asm volatile("cp.async.wait_group 1;");
        } else {
            asm volatile("cp.async.wait_group 0;");
        }
        __syncthreads();

        uint32_t buf = sb + (uint32_t)(i & 1) * 65536;
        #pragma unroll
        for (int s = 0; s < 4; s++) {
            uint32_t ca = (uint32_t)((2 * s + acb) << 4);
            uint32_t cb = (uint32_t)((2 * s + bcb) << 4);
            uint32_t ah[2][4], al[2][4];
            #pragma unroll
            for (int mf = 0; mf < 2; mf++) {
                ldmatrix_x4(ah[mf][0], ah[mf][1], ah[mf][2], ah[mf][3],
                            buf + aPre[mf] + (ca ^ aXr[mf]));
                ldmatrix_x4(al[mf][0], al[mf][1], al[mf][2], al[mf][3],
                            buf + 16384 + aPre[mf] + (ca ^ aXr[mf]));
            }
            uint32_t bh[4][4], bl[4][4];
            #pragma unroll
            for (int p = 0; p < 4; p++) {
                ldmatrix_x4(bh[p][0], bh[p][1], bh[p][2], bh[p][3],
                            buf + 32768 + bPre[p] + (cb ^ bXr[p]));
                ldmatrix_x4(bl[p][0], bl[p][1], bl[p][2], bl[p][3],
                            buf + 49152 + bPre[p] + (cb ^ bXr[p]));
            }
            #pragma unroll
            for (int mf = 0; mf < 2; mf++) {
                #pragma unroll
                for (int p = 0; p < 4; p++) {
                    mma_bf16(acc[mf][2 * p],     ah[mf], bh[p][0], bh[p][1]);
                    mma_bf16(acc[mf][2 * p + 1], ah[mf], bh[p][2], bh[p][3]);
                    mma_bf16(acc[mf][2 * p],     ah[mf], bl[p][0], bl[p][1]);
                    mma_bf16(acc[mf][2 * p + 1], ah[mf], bl[p][2], bl[p][3]);
                    mma_bf16(acc[mf][2 * p],     al[mf], bh[p][0], bh[p][1]);
                    mma_bf16(acc[mf][2 * p + 1], al[mf], bh[p][2], bh[p][3]);
                }
            }
        }
        __syncthreads();
    }

    int qr = lane >> 2, qc = (lane & 3) * 2;
    #pragma unroll
    for (int mf = 0; mf < 2; mf++) {
        #pragma unroll
        for (int half = 0; half < 2; half++) {
            int row = m0 + wm * 32 + mf * 16 + half * 8 + qr;
            #pragma unroll
            for (int nf = 0; nf < 8; nf++) {
                int col = n0 + wn * 64 + nf * 8 + qc;
                float v0 = acc[mf][nf][half * 2 + 0] + bias[col];
                float v1 = acc[mf][nf][half * 2 + 1] + bias[col + 1];
                if (ACT == 1) { v0 = gelu_exact(v0); v1 = gelu_exact(v1); }
                if (ADD) {
                    v0 += addp[(size_t)row * N + col];
                    v1 += addp[(size_t)row * N + col + 1];
                }
                if (OUTF32) {
                    *(float2*)&C[(size_t)row * N + col] = make_float2(v0, v1);
                }
                if (OUTBF16) {
                    __nv_bfloat16 h0, l0, h1, l1;
                    split_bf16(v0, h0, l0);
                    split_bf16(v1, h1, l1);
                    *(uint32_t*)&Chi[(size_t)row * N + col] = pack2(h0, h1);
                    *(uint32_t*)&Clo[(size_t)row * N + col] = pack2(l0, l1);
                }
            }
        }
    }
}

// ---------------------------------------------------------------------------
// Tensor-core flash attention v2: inputs pre-split bf16 (qkvh/qkvl),
// cp.async loads, double-buffered K/V stages. 128 q x one (b,h), 256 thr.
// Smem: Qh|Ql (32KB) + 2 stages x (Kh|Kl|Vh|Vl = 64KB) = 160KB.
// ---------------------------------------------------------------------------
#define TATTN_SMEM (32768 + 2 * 65536)   // 163840

__global__ void __launch_bounds__(256, 1)
tattn_kernel(const __nv_bfloat16* __restrict__ qkvh,
             const __nv_bfloat16* __restrict__ qkvl,
             __nv_bfloat16* __restrict__ oh,
             __nv_bfloat16* __restrict__ ol) {
    extern __shared__ char smc[];
    uint32_t sb = smem_u32(smc);

    int qt = blockIdx.x;              // 0..7
    int bh = blockIdx.y;              // 0..95
    int b = bh / HEADS, h = bh % HEADS;
    int tid = threadIdx.x, wid = tid >> 5, lane = tid & 31;
    int g = lane >> 3, lr = lane & 7;

    size_t tokb = (size_t)b * SEQ;

    // --- Q tiles (hi, lo) via cp.async ---
    #pragma unroll
    for (int it = 0; it < 4; it++) {
        int u = it * 256 + tid;
        int r = u >> 3, c = u & 7;
        size_t go = (tokb + qt * 128 + r) * QKVD + h * HD + c * 8;
        cp_async16(sb + sw_off(r, c), qkvh + go);
        cp_async16(sb + 16384 + sw_off(r, c), qkvl + go);
    }
    asm volatile("cp.async.commit_group;");

    auto load_kv = [&](int kt) {
        uint32_t stg = sb + 32768 + (uint32_t)(kt & 1) * 65536;
        #pragma unroll
        for (int it = 0; it < 4; it++) {
            int u = it * 256 + tid;
            int r = u >> 3, c = u & 7;
            size_t go = (tokb + kt * 128 + r) * QKVD + h * HD + c * 8;
            cp_async16(stg + sw_off(r, c),         qkvh + go + DIM);
            cp_async16(stg + 16384 + sw_off(r, c), qkvl + go + DIM);
            cp_async16(stg + 32768 + sw_off(r, c), qkvh + go + 2 * DIM);
            cp_async16(stg + 49152 + sw_off(r, c), qkvl + go + 2 * DIM);
        }
        asm volatile("cp.async.commit_group;");
    };

    load_kv(0);
    asm volatile("cp.async.wait_group 1;");   // Q ready
    __syncthreads();

    // --- hoist Q fragments ---
    uint32_t qh[4][4], ql[4][4];
    {
        int arow = wid * 16 + (g & 1) * 8 + lr;
        uint32_t aOff = (uint32_t)(arow * 128), aX = (uint32_t)((arow & 7) << 4);
        #pragma unroll
        for (int s = 0; s < 4; s++) {
            uint32_t ca = (uint32_t)((2 * s + (g >> 1)) << 4);
            ldmatrix_x4(qh[s][0], qh[s][1], qh[s][2], qh[s][3], sb + aOff + (ca ^ aX));
            ldmatrix_x4(ql[s][0], ql[s][1], ql[s][2], ql[s][3], sb + 16384 + aOff + (ca ^ aX));
        }
    }

    float m0 = -1e30f, m1 = -1e30f, l0 = 0.0f, l1 = 0.0f;
    float O[8][4];
    #pragma unroll
    for (int j = 0; j < 8; j++)
        #pragma unroll
        for (int q = 0; q < 4; q++) O[j][q] = 0.0f;

    for (int kt = 0; kt < 8; kt++) {
        if (kt + 1 < 8) {
            load_kv(kt + 1);
            asm volatile("cp.async.wait_group 1;");
        } else {
            asm volatile("cp.async.wait_group 0;");
        }
        __syncthreads();

        uint32_t stg = sb + 32768 + (uint32_t)(kt & 1) * 65536;

        // --- S = Q @ K^T (16 n8 frags), 3-term split ---
        float S[16][4];
        #pragma unroll
        for (int nf = 0; nf < 16; nf++)
            #pragma unroll
            for (int q = 0; q < 4; q++) S[nf][q] = 0.0f;

        #pragma unroll
        for (int s = 0; s < 4; s++) {
            #pragma unroll
            for (int p = 0; p < 8; p++) {
                int brow = p * 16 + (g >> 1) * 8 + lr;
                uint32_t bOff = (uint32_t)(brow * 128), bX = (uint32_t)((brow & 7) << 4);
                uint32_t cb = (uint32_t)((2 * s + (g & 1)) << 4);
                uint32_t kh[4], kl[4];
                ldmatrix_x4(kh[0], kh[1], kh[2], kh[3], stg + bOff + (cb ^ bX));
                ldmatrix_x4(kl[0], kl[1], kl[2], kl[3], stg + 16384 + bOff + (cb ^ bX));
                mma_bf16(S[2 * p],     qh[s], kh[0], kh[1]);
                mma_bf16(S[2 * p + 1], qh[s], kh[2], kh[3]);
                mma_bf16(S[2 * p],     qh[s], kl[0], kl[1]);
                mma_bf16(S[2 * p + 1], qh[s], kl[2], kl[3]);
                mma_bf16(S[2 * p],     ql[s], kh[0], kh[1]);
                mma_bf16(S[2 * p + 1], ql[s], kh[2], kh[3]);
            }
        }

        // apply softmax scale (1/8, exact)
        #pragma unroll
        for (int nf = 0; nf < 16; nf++) {
            S[nf][0] *= 0.125f; S[nf][1] *= 0.125f;
            S[nf][2] *= 0.125f; S[nf][3] *= 0.125f;
        }

        // --- online softmax ---
        float mt0 = -1e30f, mt1 = -1e30f;
        #pragma unroll
        for (int nf = 0; nf < 16; nf++) {
            mt0 = fmaxf(mt0, fmaxf(S[nf][0], S[nf][1]));
            mt1 = fmaxf(mt1, fmaxf(S[nf][2], S[nf][3]));
        }
        mt0 = fmaxf(mt0, __shfl_xor_sync(0xffffffffu, mt0, 1));
        mt0 = fmaxf(mt0, __shfl_xor_sync(0xffffffffu, mt0, 2));
        mt1 = fmaxf(mt1, __shfl_xor_sync(0xffffffffu, mt1, 1));
        mt1 = fmaxf(mt1, __shfl_xor_sync(0xffffffffu, mt1, 2));
        float mn0 = fmaxf(m0, mt0), mn1 = fmaxf(m1, mt1);
        float c0 = __expf(m0 - mn0), c1 = __expf(m1 - mn1);
        m0 = mn0; m1 = mn1;
        #pragma unroll
        for (int j = 0; j < 8; j++) {
            O[j][0] *= c0; O[j][1] *= c0;
            O[j][2] *= c1; O[j][3] *= c1;
        }
        float s0 = 0.0f, s1 = 0.0f;
        #pragma unroll
        for (int nf = 0; nf < 16; nf++) {
            S[nf][0] = __expf(S[nf][0] - mn0); s0 += S[nf][0];
            S[nf][1] = __expf(S[nf][1] - mn0); s0 += S[nf][1];
            S[nf][2] = __expf(S[nf][2] - mn1); s1 += S[nf][2];
            S[nf][3] = __expf(S[nf][3] - mn1); s1 += S[nf][3];
        }
        s0 += __shfl_xor_sync(0xffffffffu, s0, 1);
        s0 += __shfl_xor_sync(0xffffffffu, s0, 2);
        s1 += __shfl_xor_sync(0xffffffffu, s1, 1);
        s1 += __shfl_xor_sync(0xffffffffu, s1, 2);
        l0 = l0 * c0 + s0;
        l1 = l1 * c1 + s1;

        // --- O += P @ V, P frags from S accumulators, 3-term ---
        #pragma unroll
        for (int s = 0; s < 8; s++) {
            uint32_t ph[4], pl[4];
            #pragma unroll
            for (int q = 0; q < 2; q++) {
                float x0 = S[2 * s + q][0], x1 = S[2 * s + q][1];
                float x2 = S[2 * s + q][2], x3 = S[2 * s + q][3];
                __nv_bfloat16 hx0 = __float2bfloat16(x0), hx1 = __float2bfloat16(x1);
                __nv_bfloat16 hx2 = __float2bfloat16(x2), hx3 = __float2bfloat16(x3);
                ph[2 * q + 0] = pack2(hx0, hx1);
                ph[2 * q + 1] = pack2(hx2, hx3);
                pl[2 * q + 0] = pack2(__float2bfloat16(x0 - __bfloat162float(hx0)),
                                      __float2bfloat16(x1 - __bfloat162float(hx1)));
                pl[2 * q + 1] = pack2(__float2bfloat16(x2 - __bfloat162float(hx2)),
                                      __float2bfloat16(x3 - __bfloat162float(hx3)));
            }
            int krow = s * 16 + (g & 1) * 8 + lr;
            uint32_t vOff = (uint32_t)(krow * 128), vX = (uint32_t)((krow & 7) << 4);
            #pragma unroll
            for (int t = 0; t < 4; t++) {
                uint32_t cv = (uint32_t)((2 * t + (g >> 1)) << 4);
                uint32_t vh[4], vl[4];
                ldmatrix_x4t(vh[0], vh[1], vh[2], vh[3], stg + 32768 + vOff + (cv ^ vX));
                ldmatrix_x4t(vl[0], vl[1], vl[2], vl[3], stg + 49152 + vOff + (cv ^ vX));
                mma_bf16(O[2 * t],     ph, vh[0], vh[1]);
                mma_bf16(O[2 * t + 1], ph, vh[2], vh[3]);
                mma_bf16(O[2 * t],     ph, vl[0], vl[1]);
                mma_bf16(O[2 * t + 1], ph, vl[2], vl[3]);
                mma_bf16(O[2 * t],     pl, vh[0], vh[1]);
                mma_bf16(O[2 * t + 1], pl, vh[2], vh[3]);
            }
        }
        __syncthreads();
    }

    // --- epilogue ---
    float inv0 = 1.0f / l0, inv1 = 1.0f / l1;
    int r0 = qt * 128 + wid * 16 + (lane >> 2);
    int colb = h * HD + (lane & 3) * 2;
    #pragma unroll
    for (int j = 0; j < 8; j++) {
        int col = colb + j * 8;
        float v0 = O[j][0] * inv0, v1 = O[j][1] * inv0;
        float v2 = O[j][2] * inv1, v3 = O[j][3] * inv1;
        __nv_bfloat16 h0, lo0, h1, lo1;
        split_bf16(v0, h0, lo0); split_bf16(v1, h1, lo1);
        size_t ob0 = (tokb + r0) * DIM + col;
        *(uint32_t*)&oh[ob0] = pack2(h0, h1);
        *(uint32_t*)&ol[ob0] = pack2(lo0, lo1);
        split_bf16(v2, h0, lo0); split_bf16(v3, h1, lo1);
        size_t ob1 = (tokb + r0 + 8) * DIM + col;
        *(uint32_t*)&oh[ob1] = pack2(h0, h1);
        *(uint32_t*)&ol[ob1] = pack2(lo0, lo1);
    }
}

// ---------------------------------------------------------------------------
// Launch
// ---------------------------------------------------------------------------
extern "C" void kernel_launch(void* const* d_in, const int* in_sizes, int n_in,
                              void* d_out, int out_size) {
    const float* x       = (const float*)d_in[0];
    const float* ln1_g   = (const float*)d_in[1];
    const float* ln1_b   = (const float*)d_in[2];
    const float* qkv_w   = (const float*)d_in[3];
    const float* qkv_b   = (const float*)d_in[4];
    const float* proj_w  = (const float*)d_in[5];
    const float* proj_b  = (const float*)d_in[6];
    const float* c_qkv_w = (const float*)d_in[7];
    const float* c_qkv_b = (const float*)d_in[8];
    const float* c_proj_w= (const float*)d_in[9];
    const float* c_proj_b= (const float*)d_in[10];
    const float* cp_fc1_w= (const float*)d_in[11];
    const float* cp_fc1_b= (const float*)d_in[12];
    const float* cp_fc2_w= (const float*)d_in[13];
    const float* cp_fc2_b= (const float*)d_in[14];
    const float* P       = (const float*)d_in[15];
    const float* ln2_g   = (const float*)d_in[16];
    const float* ln2_b   = (const float*)d_in[17];
    const float* fc1_w   = (const float*)d_in[18];
    const float* fc1_b   = (const float*)d_in[19];
    const float* fc2_w   = (const float*)d_in[20];
    const float* fc2_b   = (const float*)d_in[21];

    float *n1, *rinv, *pn, *y, *z, *dmap, *cph, *xsum;
    __nv_bfloat16 *qkvh, *qkvl;
    __nv_bfloat16 *n1h, *n1l, *aoh, *aol, *zinh, *zinl, *n2h, *n2l, *hh, *hl;
    __nv_bfloat16 *wqkvh, *wqkvl, *wprojh, *wprojl, *wcqkvh, *wcqkvl, *wcprojh, *wcprojl;
    __nv_bfloat16 *wfc1h, *wfc1l, *wfc2h, *wfc2l;

    cudaGetSymbolAddress((void**)&n1,    g_n1);
    cudaGetSymbolAddress((void**)&rinv,  g_rinv);
    cudaGetSymbolAddress((void**)&pn,    g_pn);
    cudaGetSymbolAddress((void**)&qkvh,  g_qkvh);
    cudaGetSymbolAddress((void**)&qkvl,  g_qkvl);
    cudaGetSymbolAddress((void**)&y,     g_y);
    cudaGetSymbolAddress((void**)&z,     g_z);
    cudaGetSymbolAddress((void**)&dmap,  g_dmap);
    cudaGetSymbolAddress((void**)&cph,   g_cph);
    cudaGetSymbolAddress((void**)&xsum,  g_xsum);
    cudaGetSymbolAddress((void**)&n1h,   g_n1h);
    cudaGetSymbolAddress((void**)&n1l,   g_n1l);
    cudaGetSymbolAddress((void**)&aoh,   g_aoh);
    cudaGetSymbolAddress((void**)&aol,   g_aol);
    cudaGetSymbolAddress((void**)&zinh,  g_zinh);
    cudaGetSymbolAddress((void**)&zinl,  g_zinl);
    cudaGetSymbolAddress((void**)&n2h,   g_n2h);
    cudaGetSymbolAddress((void**)&n2l,   g_n2l);
    cudaGetSymbolAddress((void**)&hh,    g_hh);
    cudaGetSymbolAddress((void**)&hl,    g_hl);
    cudaGetSymbolAddress((void**)&wqkvh, g_wqkvh);
    cudaGetSymbolAddress((void**)&wqkvl, g_wqkvl);
    cudaGetSymbolAddress((void**)&wprojh, g_wprojh);
    cudaGetSymbolAddress((void**)&wprojl, g_wprojl);
    cudaGetSymbolAddress((void**)&wcqkvh, g_wcqkvh);
    cudaGetSymbolAddress((void**)&wcqkvl, g_wcqkvl);
    cudaGetSymbolAddress((void**)&wcprojh, g_wcprojh);
    cudaGetSymbolAddress((void**)&wcprojl, g_wcprojl);
    cudaGetSymbolAddress((void**)&wfc1h, g_wfc1h);
    cudaGetSymbolAddress((void**)&wfc1l, g_wfc1l);
    cudaGetSymbolAddress((void**)&wfc2h, g_wfc2h);
    cudaGetSymbolAddress((void**)&wfc2l, g_wfc2l);

    cudaFuncSetAttribute(tattn_kernel, cudaFuncAttributeMaxDynamicSharedMemorySize, TATTN_SMEM);
    cudaFuncSetAttribute(hgemm<0, false, false, true >, cudaFuncAttributeMaxDynamicSharedMemorySize, HG_SMEM);
    cudaFuncSetAttribute(hgemm<0, false, true,  false>, cudaFuncAttributeMaxDynamicSharedMemorySize, HG_SMEM);
    cudaFuncSetAttribute(hgemm<1, false, false, true >, cudaFuncAttributeMaxDynamicSharedMemorySize, HG_SMEM);
    cudaFuncSetAttribute(hgemm<0, true,  true,  false>, cudaFuncAttributeMaxDynamicSharedMemorySize, HG_SMEM);

    float* out_x = (float*)d_out;

    // 0) weight conversion fp32 -> bf16 hi/lo (vectorized x4)
    cvt_kernel<<<(QKVD * DIM / 4 + 255) / 256, 256>>>(qkv_w,   wqkvh,  wqkvl,  QKVD * DIM / 4);
    cvt_kernel<<<(DIM * DIM  / 4 + 255) / 256, 256>>>(proj_w,  wprojh, wprojl, DIM * DIM / 4);
    cvt_kernel<<<(QKVD * DIM / 4 + 255) / 256, 256>>>(c_qkv_w, wcqkvh, wcqkvl, QKVD * DIM / 4);
    cvt_kernel<<<(DIM * DIM  / 4 + 255) / 256, 256>>>(c_proj_w,wcprojh,wcprojl,DIM * DIM / 4);
    cvt_kernel<<<(MLPH * DIM / 4 + 255) / 256, 256>>>(fc1_w,   wfc1h,  wfc1l,  MLPH * DIM / 4);
    cvt_kernel<<<(DIM * MLPH / 4 + 255) / 256, 256>>>(fc2_w,   wfc2h,  wfc2l,  DIM * MLPH / 4);

    // 1) LN1 (+ norms) and Pn
    ln_kernel<<<TOK, 256>>>(x, ln1_g, ln1_b, n1, n1h, n1l, rinv);
    pn_kernel<<<KP, 256>>>(P, pn);

    // 2) branch 1 attention (qkv written as split-bf16)
    hgemm<0, false, false, true><<<dim3(QKVD / 128, TOK / 128), 256, HG_SMEM>>>(
        n1h, n1l, wqkvh, wqkvl, qkv_b, nullptr, nullptr, qkvh, qkvl, TOK, QKVD, DIM);
    tattn_kernel<<<dim3(SEQ / 128, BATCH * HEADS), 256, TATTN_SMEM>>>(qkvh, qkvl, aoh, aol);
    hgemm<0, false, true, false><<<dim3(DIM / 128, TOK / 128), 256, HG_SMEM>>>(
        aoh, aol, wprojh, wprojl, proj_b, nullptr, y, nullptr, nullptr, TOK, DIM, DIM);

    // 3) similarity map + c_project MLP (fp32)
    sgemm64<0, false, true, false><<<dim3(KP / 64, TOK / 64), 256>>>(
        n1, pn, nullptr, rinv, dmap, nullptr, nullptr, TOK, KP, DIM);
    sgemm64<1, true, false, false><<<dim3(KP / 64, TOK / 64), 256>>>(
        dmap, cp_fc1_w, cp_fc1_b, nullptr, cph, nullptr, nullptr, TOK, KP, KP);
    sgemm64<0, true, false, true><<<dim3(DIM / 64, TOK / 64), 256>>>(
        cph, cp_fc2_w, cp_fc2_b, nullptr, nullptr, zinh, zinl, TOK, DIM, KP);

    // 4) branch 2 attention
    hgemm<0, false, false, true><<<dim3(QKVD / 128, TOK / 128), 256, HG_SMEM>>>(
        zinh, zinl, wcqkvh, wcqkvl, c_qkv_b, nullptr, nullptr, qkvh, qkvl, TOK, QKVD, DIM);
    tattn_kernel<<<dim3(SEQ / 128, BATCH * HEADS), 256, TATTN_SMEM>>>(qkvh, qkvl, aoh, aol);
    hgemm<0, false, true, false><<<dim3(DIM / 128, TOK / 128), 256, HG_SMEM>>>(
        aoh, aol, wcprojh, wcprojl, c_proj_b, nullptr, z, nullptr, nullptr, TOK, DIM, DIM);

    // 5) residual sum + LN2
    addln_kernel<<<TOK, 256>>>(x, y, z, ln2_g, ln2_b, xsum, n2h, n2l);

    // 6) MLP (tensor)
    hgemm<1, false, false, true><<<dim3(MLPH / 128, TOK / 128), 256, HG_SMEM>>>(
        n2h, n2l, wfc1h, wfc1l, fc1_b, nullptr, nullptr, hh, hl, TOK, MLPH, DIM);
    hgemm<0, true, true, false><<<dim3(DIM / 128, TOK / 128), 256, HG_SMEM>>>(
        hh, hl, wfc2h, wfc2l, fc2_b, xsum, out_x, nullptr, nullptr, TOK, DIM, MLPH);

    // 7) dmap output
    if (out_size >= TOK * DIM + TOK * KP) {
        cudaMemcpyAsync(out_x + (size_t)TOK * DIM, dmap,
                        (size_t)TOK * KP * sizeof(float),
                        cudaMemcpyDeviceToDevice);
    }
}